// round 15
// baseline (speedup 1.0000x reference)
#include <cuda_runtime.h>
#include <cuda_fp16.h>
#include <math.h>
#include <stdint.h>

#define NTOK 4096
#define HDIM 1024
#define FDIM 4096
#define NE   8

#define BM 128
#define BN 128
#define BK 64
#define NSTAGE 3
#define AW 36                              // words per A row (64 halves + pad)
#define BW 68                              // words per B k-row (128 halves + pad)
#define A_WORDS (BM * AW)                  // 4608
#define B_WORDS (BK * BW)                  // 4352
#define STAGE_WORDS (A_WORDS + B_WORDS)    // 8960 (35840 B)
#define DYN_SMEM (NSTAGE * STAGE_WORDS * 4)  // 107520 bytes

// ---------------- device scratch ----------------
__device__ int   g_count[NE];
__device__ int   g_off[NE];
__device__ int   g_tok[NE * NTOK];
__device__ float g_wt[NE * NTOK];
__device__ float g_zsq[NTOK];
__device__ float g_wa[NTOK];
__device__ float g_wb[NTOK];
__device__ float g_ma[NTOK];
__device__ float g_mb[NTOK];
__device__ float g_part[16 * 5];
__device__ __align__(16) __half g_h1f[(size_t)2 * NTOK * FDIM];   // 64 MiB
__device__ __align__(16) __half g_xh[(size_t)NTOK * HDIM];        // 8 MiB
__device__ __align__(16) __half g_w1h[(size_t)NE * HDIM * FDIM];  // 64 MiB: [E][H][F]
__device__ __align__(16) __half g_w2h[(size_t)NE * FDIM * HDIM];  // 64 MiB: [E][F][H]

// ---------------- helpers ----------------
__device__ __forceinline__ unsigned su32(const void* p) {
    return (unsigned)__cvta_generic_to_shared(p);
}
__device__ __forceinline__ void cp_async16(unsigned dst, const void* src) {
    asm volatile("cp.async.cg.shared.global [%0], [%1], 16;" :: "r"(dst), "l"(src));
}
__device__ __forceinline__ void cp_commit() {
    asm volatile("cp.async.commit_group;" ::: "memory");
}
template<int N> __device__ __forceinline__ void cp_wait() {
    asm volatile("cp.async.wait_group %0;" :: "n"(N) : "memory");
}
__device__ __forceinline__ void ldsm4(unsigned* r, unsigned a) {
    asm volatile("ldmatrix.sync.aligned.m8n8.x4.shared.b16 {%0,%1,%2,%3}, [%4];"
                 : "=r"(r[0]), "=r"(r[1]), "=r"(r[2]), "=r"(r[3]) : "r"(a));
}
__device__ __forceinline__ void ldsm4t(unsigned* r, unsigned a) {
    asm volatile("ldmatrix.sync.aligned.m8n8.x4.trans.shared.b16 {%0,%1,%2,%3}, [%4];"
                 : "=r"(r[0]), "=r"(r[1]), "=r"(r[2]), "=r"(r[3]) : "r"(a));
}
__device__ __forceinline__ void mma16(float* d, const unsigned* a, const unsigned* b) {
    asm volatile(
        "mma.sync.aligned.m16n8k16.row.col.f32.f16.f16.f32 "
        "{%0,%1,%2,%3}, {%4,%5,%6,%7}, {%8,%9}, {%0,%1,%2,%3};"
        : "+f"(d[0]), "+f"(d[1]), "+f"(d[2]), "+f"(d[3])
        : "r"(a[0]), "r"(a[1]), "r"(a[2]), "r"(a[3]), "r"(b[0]), "r"(b[1]));
}
__device__ __forceinline__ float silu_f(float v) { return v / (1.0f + expf(-v)); }

// ---------------- small kernels ----------------
__global__ void zero_kernel(float* out, int n) {
    for (int i = blockIdx.x * blockDim.x + threadIdx.x; i < n; i += gridDim.x * blockDim.x)
        out[i] = 0.0f;
}
__global__ void reset_kernel() {
    if (threadIdx.x < NE) g_count[threadIdx.x] = 0;
}
__global__ void cvt16_kernel(const float* __restrict__ in, __half* __restrict__ out, size_t n) {
    size_t i0 = ((size_t)blockIdx.x * blockDim.x + threadIdx.x) * 8;
    size_t stride = (size_t)gridDim.x * blockDim.x * 8;
    for (size_t i = i0; i < n; i += stride) {
        float4 v = *(const float4*)(in + i);
        float4 u = *(const float4*)(in + i + 4);
        __half2 h0 = __floats2half2_rn(v.x, v.y);
        __half2 h1 = __floats2half2_rn(v.z, v.w);
        __half2 h2 = __floats2half2_rn(u.x, u.y);
        __half2 h3 = __floats2half2_rn(u.z, u.w);
        uint4 o;
        o.x = *(unsigned*)&h0; o.y = *(unsigned*)&h1;
        o.z = *(unsigned*)&h2; o.w = *(unsigned*)&h3;
        *(uint4*)(out + i) = o;
    }
}

// router: one warp per token
__global__ void router_kernel(const float* __restrict__ x, const float* __restrict__ gw) {
    int warp = threadIdx.x >> 5;
    int lane = threadIdx.x & 31;
    int t = blockIdx.x * (blockDim.x >> 5) + warp;
    if (t >= NTOK) return;

    float p[NE];
#pragma unroll
    for (int e = 0; e < NE; e++) p[e] = 0.0f;
    const float* xr = x + (size_t)t * HDIM;
    for (int h = lane; h < HDIM; h += 32) {
        float xv = xr[h];
#pragma unroll
        for (int e = 0; e < NE; e++) p[e] += xv * gw[e * HDIM + h];
    }
#pragma unroll
    for (int e = 0; e < NE; e++) {
#pragma unroll
        for (int s = 16; s > 0; s >>= 1) p[e] += __shfl_xor_sync(0xffffffffu, p[e], s);
    }
    if (lane == 0) {
        float m = p[0];
#pragma unroll
        for (int e = 1; e < NE; e++) m = fmaxf(m, p[e]);
        float Z = 0.0f; float pr[NE];
#pragma unroll
        for (int e = 0; e < NE; e++) { pr[e] = expf(p[e] - m); Z += pr[e]; }
        float invZ = 1.0f / Z;
#pragma unroll
        for (int e = 0; e < NE; e++) pr[e] *= invZ;
        int e1 = 0; float v1 = pr[0];
#pragma unroll
        for (int e = 1; e < NE; e++) if (pr[e] > v1) { v1 = pr[e]; e1 = e; }
        int e2 = -1; float v2 = -1.0f;
#pragma unroll
        for (int e = 0; e < NE; e++) if (e != e1 && pr[e] > v2) { v2 = pr[e]; e2 = e; }
        float s = v1 + v2;
        float lse = m + logf(Z);
        g_zsq[t] = lse * lse;
        g_wa[t] = v1; g_wb[t] = v2;
        g_ma[t] = (e1 == 0 || e2 == 0) ? 1.0f : 0.0f;
        g_mb[t] = (e1 == 1 || e2 == 1) ? 1.0f : 0.0f;
        int s1 = atomicAdd(&g_count[e1], 1);
        g_tok[e1 * NTOK + s1] = t; g_wt[e1 * NTOK + s1] = v1 / s;
        int s2 = atomicAdd(&g_count[e2], 1);
        g_tok[e2 * NTOK + s2] = t; g_wt[e2 * NTOK + s2] = v2 / s;
    }
}

// stage 1: 16 blocks of deterministic partial sums
__global__ void partial_kernel() {
    int tid = threadIdx.x, blk = blockIdx.x;
    float s[5] = {0, 0, 0, 0, 0};
    for (int i = blk * 256 + tid; i < NTOK; i += 16 * 256) {
        s[0] += g_zsq[i]; s[1] += g_wa[i]; s[2] += g_wb[i];
        s[3] += g_ma[i];  s[4] += g_mb[i];
    }
    __shared__ float red[256];
#pragma unroll
    for (int q = 0; q < 5; q++) {
        red[tid] = s[q];
        __syncthreads();
        for (int st = 128; st > 0; st >>= 1) {
            if (tid < st) red[tid] += red[tid + st];
            __syncthreads();
        }
        if (tid == 0) g_part[blk * 5 + q] = red[0];
        __syncthreads();
    }
}

// stage 2: one thread reduces partials, emits losses + offsets
__global__ void finalize_kernel(float* out, int out_size) {
    if (threadIdx.x == 0) {
        float tot[5] = {0, 0, 0, 0, 0};
        for (int b = 0; b < 16; b++)
#pragma unroll
            for (int q = 0; q < 5; q++) tot[q] += g_part[b * 5 + q];
        const float invT = 1.0f / (float)NTOK;
        float zl  = tot[0] * invT;
        float aux = 2.0f * ((tot[3] * invT) * (tot[1] * invT) +
                            (tot[4] * invT) * (tot[2] * invT));
        long long base = (long long)NTOK * HDIM;
        if ((long long)out_size > base)     out[base]     = zl;
        if ((long long)out_size > base + 1) out[base + 1] = aux;
        int o = 0;
        for (int e = 0; e < NE; e++) { g_off[e] = o; o += g_count[e]; }
    }
}

// =====================================================================
// fp16 mma.sync grouped GEMMs. Block 128x128xBK64, 4 warps (2x2),
// warp tile 64x64, m16n8k16, ldmatrix fragment loads, 3-stage cp.async.
// A smem: [BM][AW] k-major (LDSM). B smem: [BK][BW] n-contig k-rows
// (LDSM .trans). Row strides 36/68 words -> conflict-free LDSM.
// =====================================================================

// GEMM1: h1f[off+m][n] = fp16(silu( sum_k xh[tok[m]][k] * w1h[e][k][n] + b1[e][n] ))
__global__ void __launch_bounds__(128, 2)
gemm1_kernel(const float* __restrict__ b1) {
    int e = blockIdx.z;
    int cnt = g_count[e];
    int m0 = blockIdx.y * BM;
    if (m0 >= cnt) return;
    int n0 = blockIdx.x * BN;
    int off = g_off[e];

    extern __shared__ unsigned smw[];
    __shared__ int toks[BM];

    int tid = threadIdx.x;
    int wid = tid >> 5, lane = tid & 31;

    if (tid < BM) {
        int r = m0 + tid; if (r > cnt - 1) r = cnt - 1;
        toks[tid] = g_tok[e * NTOK + r];
    }
    __syncthreads();

    unsigned sbase = su32(smw);
    // cp.async slots: 8 A + 8 B chunks of 16B per thread per stage
    unsigned adst[8], bdst[8];
    const char* asrc[8];
    const char* bsrc[8];
#pragma unroll
    for (int j = 0; j < 8; j++) {
        int idx = tid + 128 * j;
        int arow = idx >> 3, ach = idx & 7;         // A: 128 rows x 8 chunks (128B/row)
        adst[j] = sbase + (arow * AW + ach * 4) * 4;
        asrc[j] = (const char*)(g_xh + (size_t)toks[arow] * HDIM) + ach * 16;
        int brow = idx >> 4, bch = idx & 15;        // B: 64 k-rows x 16 chunks (256B/row)
        bdst[j] = sbase + (A_WORDS + brow * BW + bch * 4) * 4;
        bsrc[j] = (const char*)(g_w1h + (size_t)e * HDIM * FDIM + (size_t)brow * FDIM + n0) + bch * 16;
    }
    const size_t aadv = (size_t)BK * 2;             // 128 B per kt
    const size_t badv = (size_t)BK * FDIM * 2;

    int wm = wid >> 1, wn = wid & 1;
    int t8 = lane >> 3, rit = lane & 7;
    unsigned a_lane = ((wm * 64 + (t8 & 1) * 8 + rit) * AW + (t8 >> 1) * 4) * 4;
    unsigned b_lane = A_WORDS * 4 + ((t8 & 1) * 8 + rit) * (BW * 4) + (wn * 64 + (t8 >> 1) * 8) * 2;

    float acc[4][8][4];
#pragma unroll
    for (int i = 0; i < 4; i++)
#pragma unroll
        for (int j = 0; j < 8; j++)
#pragma unroll
            for (int q = 0; q < 4; q++) acc[i][j][q] = 0.0f;

    const int NKT = HDIM / BK;  // 16
#pragma unroll
    for (int s = 0; s < NSTAGE - 1; s++) {
        unsigned so = s * STAGE_WORDS * 4;
#pragma unroll
        for (int j = 0; j < 8; j++) {
            cp_async16(adst[j] + so, asrc[j] + (size_t)s * aadv);
            cp_async16(bdst[j] + so, bsrc[j] + (size_t)s * badv);
        }
        cp_commit();
    }

    int r = lane >> 2, c = lane & 3;

    for (int kt = 0; kt < NKT; kt++) {
        if (kt == NKT - 1) cp_wait<0>(); else cp_wait<1>();
        __syncthreads();

        if (kt + 2 < NKT) {
            unsigned so = ((kt + 2) % NSTAGE) * STAGE_WORDS * 4;
            size_t ka = (size_t)(kt + 2) * aadv;
            size_t kb = (size_t)(kt + 2) * badv;
#pragma unroll
            for (int j = 0; j < 8; j++) {
                cp_async16(adst[j] + so, asrc[j] + ka);
                cp_async16(bdst[j] + so, bsrc[j] + kb);
            }
            cp_commit();
        }

        unsigned sb = sbase + (kt % NSTAGE) * STAGE_WORDS * 4;
#pragma unroll
        for (int ks = 0; ks < 4; ks++) {
            unsigned af[4][4], bf[8][2];
#pragma unroll
            for (int i = 0; i < 4; i++)
                ldsm4(af[i], sb + a_lane + (i * 16 * AW + ks * 8) * 4);
#pragma unroll
            for (int jp = 0; jp < 4; jp++) {
                unsigned rr[4];
                ldsm4t(rr, sb + b_lane + ks * 16 * (BW * 4) + jp * 32);
                bf[2 * jp][0] = rr[0]; bf[2 * jp][1] = rr[1];
                bf[2 * jp + 1][0] = rr[2]; bf[2 * jp + 1][1] = rr[3];
            }
#pragma unroll
            for (int i = 0; i < 4; i++)
#pragma unroll
                for (int j = 0; j < 8; j++) mma16(acc[i][j], af[i], bf[j]);
        }
        __syncthreads();
    }

    // epilogue: bias + silu -> fp16
#pragma unroll
    for (int i = 0; i < 4; i++) {
        int mrowA = m0 + wm * 64 + i * 16 + r;
        int mrowB = mrowA + 8;
#pragma unroll
        for (int j = 0; j < 8; j++) {
            int ncol = n0 + wn * 64 + j * 8 + c * 2;
            float2 bb = *(const float2*)&b1[(size_t)e * FDIM + ncol];
            if (mrowA < cnt) {
                __half2 h = __floats2half2_rn(silu_f(acc[i][j][0] + bb.x),
                                              silu_f(acc[i][j][1] + bb.y));
                *(__half2*)&g_h1f[(size_t)(off + mrowA) * FDIM + ncol] = h;
            }
            if (mrowB < cnt) {
                __half2 h = __floats2half2_rn(silu_f(acc[i][j][2] + bb.x),
                                              silu_f(acc[i][j][3] + bb.y));
                *(__half2*)&g_h1f[(size_t)(off + mrowB) * FDIM + ncol] = h;
            }
        }
    }
}

// GEMM2: out[tok[m]][n] += wt[m] * ( sum_k h1f[off+m][k] * w2h[e][k][n] + b2[e][n] )
__global__ void __launch_bounds__(128, 2)
gemm2_kernel(const float* __restrict__ b2, float* __restrict__ out) {
    int e = blockIdx.z;
    int cnt = g_count[e];
    int m0 = blockIdx.y * BM;
    if (m0 >= cnt) return;
    int n0 = blockIdx.x * BN;
    int off = g_off[e];

    extern __shared__ unsigned smw[];
    __shared__ int tks[BM];
    __shared__ float wts[BM];

    int tid = threadIdx.x;
    int wid = tid >> 5, lane = tid & 31;

    if (tid < BM) {
        int r = m0 + tid; if (r > cnt - 1) r = cnt - 1;
        tks[tid] = g_tok[e * NTOK + r];
        wts[tid] = g_wt[e * NTOK + r];
    }
    __syncthreads();

    unsigned sbase = su32(smw);
    unsigned adst[8], bdst[8];
    const char* asrc[8];
    const char* bsrc[8];
#pragma unroll
    for (int j = 0; j < 8; j++) {
        int idx = tid + 128 * j;
        int arow = idx >> 3, ach = idx & 7;
        int rr = m0 + arow; if (rr > cnt - 1) rr = cnt - 1;
        adst[j] = sbase + (arow * AW + ach * 4) * 4;
        asrc[j] = (const char*)(g_h1f + (size_t)(off + rr) * FDIM) + ach * 16;
        int brow = idx >> 4, bch = idx & 15;
        bdst[j] = sbase + (A_WORDS + brow * BW + bch * 4) * 4;
        bsrc[j] = (const char*)(g_w2h + (size_t)e * FDIM * HDIM + (size_t)brow * HDIM + n0) + bch * 16;
    }
    const size_t aadv = (size_t)BK * 2;
    const size_t badv = (size_t)BK * HDIM * 2;

    int wm = wid >> 1, wn = wid & 1;
    int t8 = lane >> 3, rit = lane & 7;
    unsigned a_lane = ((wm * 64 + (t8 & 1) * 8 + rit) * AW + (t8 >> 1) * 4) * 4;
    unsigned b_lane = A_WORDS * 4 + ((t8 & 1) * 8 + rit) * (BW * 4) + (wn * 64 + (t8 >> 1) * 8) * 2;

    float acc[4][8][4];
#pragma unroll
    for (int i = 0; i < 4; i++)
#pragma unroll
        for (int j = 0; j < 8; j++)
#pragma unroll
            for (int q = 0; q < 4; q++) acc[i][j][q] = 0.0f;

    const int NKT = FDIM / BK;  // 64
#pragma unroll
    for (int s = 0; s < NSTAGE - 1; s++) {
        unsigned so = s * STAGE_WORDS * 4;
#pragma unroll
        for (int j = 0; j < 8; j++) {
            cp_async16(adst[j] + so, asrc[j] + (size_t)s * aadv);
            cp_async16(bdst[j] + so, bsrc[j] + (size_t)s * badv);
        }
        cp_commit();
    }

    int r = lane >> 2, c = lane & 3;

    for (int kt = 0; kt < NKT; kt++) {
        if (kt == NKT - 1) cp_wait<0>(); else cp_wait<1>();
        __syncthreads();

        if (kt + 2 < NKT) {
            unsigned so = ((kt + 2) % NSTAGE) * STAGE_WORDS * 4;
            size_t ka = (size_t)(kt + 2) * aadv;
            size_t kb = (size_t)(kt + 2) * badv;
#pragma unroll
            for (int j = 0; j < 8; j++) {
                cp_async16(adst[j] + so, asrc[j] + ka);
                cp_async16(bdst[j] + so, bsrc[j] + kb);
            }
            cp_commit();
        }

        unsigned sb = sbase + (kt % NSTAGE) * STAGE_WORDS * 4;
#pragma unroll
        for (int ks = 0; ks < 4; ks++) {
            unsigned af[4][4], bf[8][2];
#pragma unroll
            for (int i = 0; i < 4; i++)
                ldsm4(af[i], sb + a_lane + (i * 16 * AW + ks * 8) * 4);
#pragma unroll
            for (int jp = 0; jp < 4; jp++) {
                unsigned rr[4];
                ldsm4t(rr, sb + b_lane + ks * 16 * (BW * 4) + jp * 32);
                bf[2 * jp][0] = rr[0]; bf[2 * jp][1] = rr[1];
                bf[2 * jp + 1][0] = rr[2]; bf[2 * jp + 1][1] = rr[3];
            }
#pragma unroll
            for (int i = 0; i < 4; i++)
#pragma unroll
                for (int j = 0; j < 8; j++) mma16(acc[i][j], af[i], bf[j]);
        }
        __syncthreads();
    }

#pragma unroll
    for (int i = 0; i < 4; i++) {
        int lrowA = wm * 64 + i * 16 + r;
        int lrowB = lrowA + 8;
        int mrowA = m0 + lrowA, mrowB = m0 + lrowB;
#pragma unroll
        for (int j = 0; j < 8; j++) {
            int ncol = n0 + wn * 64 + j * 8 + c * 2;
            float2 bb = *(const float2*)&b2[(size_t)e * HDIM + ncol];
            if (mrowA < cnt) {
                float w = wts[lrowA];
                float* op = out + (size_t)tks[lrowA] * HDIM + ncol;
                atomicAdd(op + 0, w * (acc[i][j][0] + bb.x));
                atomicAdd(op + 1, w * (acc[i][j][1] + bb.y));
            }
            if (mrowB < cnt) {
                float w = wts[lrowB];
                float* op = out + (size_t)tks[lrowB] * HDIM + ncol;
                atomicAdd(op + 0, w * (acc[i][j][2] + bb.x));
                atomicAdd(op + 1, w * (acc[i][j][3] + bb.y));
            }
        }
    }
}

// ---------------- launch ----------------
extern "C" void kernel_launch(void* const* d_in, const int* in_sizes, int n_in,
                              void* d_out, int out_size) {
    const float* x  = (const float*)d_in[0];
    const float* gw = (const float*)d_in[1];
    const float* w1 = (const float*)d_in[2];
    const float* b1 = (const float*)d_in[3];
    const float* w2 = (const float*)d_in[4];
    const float* b2 = (const float*)d_in[5];
    float* out = (float*)d_out;

    cudaFuncSetAttribute(gemm1_kernel, cudaFuncAttributeMaxDynamicSharedMemorySize, DYN_SMEM);
    cudaFuncSetAttribute(gemm2_kernel, cudaFuncAttributeMaxDynamicSharedMemorySize, DYN_SMEM);

    __half* xh;  cudaGetSymbolAddress((void**)&xh,  g_xh);
    __half* w1h; cudaGetSymbolAddress((void**)&w1h, g_w1h);
    __half* w2h; cudaGetSymbolAddress((void**)&w2h, g_w2h);

    zero_kernel<<<2048, 256>>>(out, out_size);
    reset_kernel<<<1, 32>>>();
    cvt16_kernel<<<1024, 256>>>(x, xh, (size_t)NTOK * HDIM);
    cvt16_kernel<<<4096, 256>>>(w1, w1h, (size_t)NE * HDIM * FDIM);
    cvt16_kernel<<<4096, 256>>>(w2, w2h, (size_t)NE * FDIM * HDIM);
    router_kernel<<<NTOK / 8, 256>>>(x, gw);
    partial_kernel<<<16, 256>>>();
    finalize_kernel<<<1, 32>>>(out, out_size);
    gemm1_kernel<<<dim3(FDIM / BN, NTOK / BM, NE), 128, DYN_SMEM>>>(b1);
    gemm2_kernel<<<dim3(HDIM / BN, NTOK / BM, NE), 128, DYN_SMEM>>>(b2, out);
}

// round 16
// speedup vs baseline: 1.0815x; 1.0815x over previous
#include <cuda_runtime.h>
#include <cuda_fp16.h>
#include <math.h>
#include <stdint.h>

#define NTOK 4096
#define HDIM 1024
#define FDIM 4096
#define NE   8

#define BM 128
#define BN 128
#define BK 32
#define NSTAGE 4
#define AW 20                              // words per A row (32 halves + pad)
#define BW 68                              // words per B k-row (128 halves + pad)
#define A_WORDS (BM * AW)                  // 2560
#define B_WORDS (BK * BW)                  // 2176
#define STAGE_WORDS (A_WORDS + B_WORDS)    // 4736 (18944 B)
#define DYN_SMEM (NSTAGE * STAGE_WORDS * 4)  // 75776 bytes

// ---------------- device scratch ----------------
__device__ int   g_count[NE];
__device__ int   g_off[NE];
__device__ int   g_tok[NE * NTOK];
__device__ float g_wt[NE * NTOK];
__device__ float g_zsq[NTOK];
__device__ float g_wa[NTOK];
__device__ float g_wb[NTOK];
__device__ float g_ma[NTOK];
__device__ float g_mb[NTOK];
__device__ float g_part[16 * 5];
__device__ __align__(16) __half g_h1f[(size_t)2 * NTOK * FDIM];   // 64 MiB
__device__ __align__(16) __half g_xh[(size_t)NTOK * HDIM];        // 8 MiB
__device__ __align__(16) __half g_w1h[(size_t)NE * HDIM * FDIM];  // 64 MiB: [E][H][F]
__device__ __align__(16) __half g_w2h[(size_t)NE * FDIM * HDIM];  // 64 MiB: [E][F][H]

// ---------------- helpers ----------------
__device__ __forceinline__ unsigned su32(const void* p) {
    return (unsigned)__cvta_generic_to_shared(p);
}
__device__ __forceinline__ void cp_async16(unsigned dst, const void* src) {
    asm volatile("cp.async.cg.shared.global [%0], [%1], 16;" :: "r"(dst), "l"(src));
}
__device__ __forceinline__ void cp_commit() {
    asm volatile("cp.async.commit_group;" ::: "memory");
}
template<int N> __device__ __forceinline__ void cp_wait() {
    asm volatile("cp.async.wait_group %0;" :: "n"(N) : "memory");
}
__device__ __forceinline__ void ldsm4(unsigned* r, unsigned a) {
    asm volatile("ldmatrix.sync.aligned.m8n8.x4.shared.b16 {%0,%1,%2,%3}, [%4];"
                 : "=r"(r[0]), "=r"(r[1]), "=r"(r[2]), "=r"(r[3]) : "r"(a));
}
__device__ __forceinline__ void ldsm4t(unsigned* r, unsigned a) {
    asm volatile("ldmatrix.sync.aligned.m8n8.x4.trans.shared.b16 {%0,%1,%2,%3}, [%4];"
                 : "=r"(r[0]), "=r"(r[1]), "=r"(r[2]), "=r"(r[3]) : "r"(a));
}
__device__ __forceinline__ void mma16(float* d, const unsigned* a, const unsigned* b) {
    asm volatile(
        "mma.sync.aligned.m16n8k16.row.col.f32.f16.f16.f32 "
        "{%0,%1,%2,%3}, {%4,%5,%6,%7}, {%8,%9}, {%0,%1,%2,%3};"
        : "+f"(d[0]), "+f"(d[1]), "+f"(d[2]), "+f"(d[3])
        : "r"(a[0]), "r"(a[1]), "r"(a[2]), "r"(a[3]), "r"(b[0]), "r"(b[1]));
}
__device__ __forceinline__ float silu_f(float v) { return v / (1.0f + expf(-v)); }

// ---------------- small kernels ----------------
__global__ void zero_kernel(float* out, int n) {
    for (int i = blockIdx.x * blockDim.x + threadIdx.x; i < n; i += gridDim.x * blockDim.x)
        out[i] = 0.0f;
}
__global__ void reset_kernel() {
    if (threadIdx.x < NE) g_count[threadIdx.x] = 0;
}
__global__ void cvt16_kernel(const float* __restrict__ in, __half* __restrict__ out, size_t n) {
    size_t i0 = ((size_t)blockIdx.x * blockDim.x + threadIdx.x) * 8;
    size_t stride = (size_t)gridDim.x * blockDim.x * 8;
    for (size_t i = i0; i < n; i += stride) {
        float4 v = *(const float4*)(in + i);
        float4 u = *(const float4*)(in + i + 4);
        __half2 h0 = __floats2half2_rn(v.x, v.y);
        __half2 h1 = __floats2half2_rn(v.z, v.w);
        __half2 h2 = __floats2half2_rn(u.x, u.y);
        __half2 h3 = __floats2half2_rn(u.z, u.w);
        uint4 o;
        o.x = *(unsigned*)&h0; o.y = *(unsigned*)&h1;
        o.z = *(unsigned*)&h2; o.w = *(unsigned*)&h3;
        *(uint4*)(out + i) = o;
    }
}

// router: one warp per token
__global__ void router_kernel(const float* __restrict__ x, const float* __restrict__ gw) {
    int warp = threadIdx.x >> 5;
    int lane = threadIdx.x & 31;
    int t = blockIdx.x * (blockDim.x >> 5) + warp;
    if (t >= NTOK) return;

    float p[NE];
#pragma unroll
    for (int e = 0; e < NE; e++) p[e] = 0.0f;
    const float* xr = x + (size_t)t * HDIM;
    for (int h = lane; h < HDIM; h += 32) {
        float xv = xr[h];
#pragma unroll
        for (int e = 0; e < NE; e++) p[e] += xv * gw[e * HDIM + h];
    }
#pragma unroll
    for (int e = 0; e < NE; e++) {
#pragma unroll
        for (int s = 16; s > 0; s >>= 1) p[e] += __shfl_xor_sync(0xffffffffu, p[e], s);
    }
    if (lane == 0) {
        float m = p[0];
#pragma unroll
        for (int e = 1; e < NE; e++) m = fmaxf(m, p[e]);
        float Z = 0.0f; float pr[NE];
#pragma unroll
        for (int e = 0; e < NE; e++) { pr[e] = expf(p[e] - m); Z += pr[e]; }
        float invZ = 1.0f / Z;
#pragma unroll
        for (int e = 0; e < NE; e++) pr[e] *= invZ;
        int e1 = 0; float v1 = pr[0];
#pragma unroll
        for (int e = 1; e < NE; e++) if (pr[e] > v1) { v1 = pr[e]; e1 = e; }
        int e2 = -1; float v2 = -1.0f;
#pragma unroll
        for (int e = 0; e < NE; e++) if (e != e1 && pr[e] > v2) { v2 = pr[e]; e2 = e; }
        float s = v1 + v2;
        float lse = m + logf(Z);
        g_zsq[t] = lse * lse;
        g_wa[t] = v1; g_wb[t] = v2;
        g_ma[t] = (e1 == 0 || e2 == 0) ? 1.0f : 0.0f;
        g_mb[t] = (e1 == 1 || e2 == 1) ? 1.0f : 0.0f;
        int s1 = atomicAdd(&g_count[e1], 1);
        g_tok[e1 * NTOK + s1] = t; g_wt[e1 * NTOK + s1] = v1 / s;
        int s2 = atomicAdd(&g_count[e2], 1);
        g_tok[e2 * NTOK + s2] = t; g_wt[e2 * NTOK + s2] = v2 / s;
    }
}

// stage 1: 16 blocks of deterministic partial sums
__global__ void partial_kernel() {
    int tid = threadIdx.x, blk = blockIdx.x;
    float s[5] = {0, 0, 0, 0, 0};
    for (int i = blk * 256 + tid; i < NTOK; i += 16 * 256) {
        s[0] += g_zsq[i]; s[1] += g_wa[i]; s[2] += g_wb[i];
        s[3] += g_ma[i];  s[4] += g_mb[i];
    }
    __shared__ float red[256];
#pragma unroll
    for (int q = 0; q < 5; q++) {
        red[tid] = s[q];
        __syncthreads();
        for (int st = 128; st > 0; st >>= 1) {
            if (tid < st) red[tid] += red[tid + st];
            __syncthreads();
        }
        if (tid == 0) g_part[blk * 5 + q] = red[0];
        __syncthreads();
    }
}

// stage 2: one thread reduces partials, emits losses + offsets
__global__ void finalize_kernel(float* out, int out_size) {
    if (threadIdx.x == 0) {
        float tot[5] = {0, 0, 0, 0, 0};
        for (int b = 0; b < 16; b++)
#pragma unroll
            for (int q = 0; q < 5; q++) tot[q] += g_part[b * 5 + q];
        const float invT = 1.0f / (float)NTOK;
        float zl  = tot[0] * invT;
        float aux = 2.0f * ((tot[3] * invT) * (tot[1] * invT) +
                            (tot[4] * invT) * (tot[2] * invT));
        long long base = (long long)NTOK * HDIM;
        if ((long long)out_size > base)     out[base]     = zl;
        if ((long long)out_size > base + 1) out[base + 1] = aux;
        int o = 0;
        for (int e = 0; e < NE; e++) { g_off[e] = o; o += g_count[e]; }
    }
}

// =====================================================================
// fp16 mma.sync grouped GEMMs. Block 128x128xBK32, 4 warps (2x2),
// warp tile 64x64, m16n8k16, ldmatrix fragment loads (all 16 LDSM per
// k-iter batched up-front for MLP), 4-stage cp.async, 1 sync/iter.
// =====================================================================

// GEMM1: h1f[off+m][n] = fp16(silu( sum_k xh[tok[m]][k] * w1h[e][k][n] + b1[e][n] ))
__global__ void __launch_bounds__(128, 2)
gemm1_kernel(const float* __restrict__ b1) {
    int e = blockIdx.z;
    int cnt = g_count[e];
    int m0 = blockIdx.y * BM;
    if (m0 >= cnt) return;
    int n0 = blockIdx.x * BN;
    int off = g_off[e];

    extern __shared__ unsigned smw[];
    __shared__ int toks[BM];

    int tid = threadIdx.x;
    int wid = tid >> 5, lane = tid & 31;

    if (tid < BM) {
        int r = m0 + tid; if (r > cnt - 1) r = cnt - 1;
        toks[tid] = g_tok[e * NTOK + r];
    }
    __syncthreads();

    unsigned sbase = su32(smw);
    unsigned adst[4], bdst[4];
    const char* asrc[4];
    const char* bsrc[4];
#pragma unroll
    for (int j = 0; j < 4; j++) {
        int idx = tid + 128 * j;
        int arow = idx >> 2, ach = idx & 3;         // A: 128 rows x 4 chunks
        adst[j] = sbase + (arow * AW + ach * 4) * 4;
        asrc[j] = (const char*)(g_xh + (size_t)toks[arow] * HDIM) + ach * 16;
        int brow = idx >> 4, bch = idx & 15;        // B: 32 k-rows x 16 chunks
        bdst[j] = sbase + (A_WORDS + brow * BW + bch * 4) * 4;
        bsrc[j] = (const char*)(g_w1h + (size_t)e * HDIM * FDIM + (size_t)brow * FDIM + n0) + bch * 16;
    }
    const size_t aadv = (size_t)BK * 2;
    const size_t badv = (size_t)BK * FDIM * 2;

    int wm = wid >> 1, wn = wid & 1;
    int t8 = lane >> 3, rit = lane & 7;
    unsigned a_lane = ((wm * 64 + (t8 & 1) * 8 + rit) * AW + (t8 >> 1) * 4) * 4;
    unsigned b_lane = A_WORDS * 4 + ((t8 & 1) * 8 + rit) * (BW * 4) + (wn * 64 + (t8 >> 1) * 8) * 2;

    float acc[4][8][4];
#pragma unroll
    for (int i = 0; i < 4; i++)
#pragma unroll
        for (int j = 0; j < 8; j++)
#pragma unroll
            for (int q = 0; q < 4; q++) acc[i][j][q] = 0.0f;

    const int NKT = HDIM / BK;  // 32
#pragma unroll
    for (int s = 0; s < NSTAGE - 1; s++) {
        unsigned so = s * STAGE_WORDS * 4;
#pragma unroll
        for (int j = 0; j < 4; j++) {
            cp_async16(adst[j] + so, asrc[j] + (size_t)s * aadv);
            cp_async16(bdst[j] + so, bsrc[j] + (size_t)s * badv);
        }
        cp_commit();
    }

    int r = lane >> 2, c = lane & 3;

    for (int kt = 0; kt < NKT; kt++) {
        if (kt < NKT - 2) cp_wait<2>();
        else if (kt == NKT - 2) cp_wait<1>();
        else cp_wait<0>();
        __syncthreads();

        if (kt + 3 < NKT) {
            unsigned so = ((kt + 3) % NSTAGE) * STAGE_WORDS * 4;
            size_t ka = (size_t)(kt + 3) * aadv;
            size_t kb = (size_t)(kt + 3) * badv;
#pragma unroll
            for (int j = 0; j < 4; j++) {
                cp_async16(adst[j] + so, asrc[j] + ka);
                cp_async16(bdst[j] + so, bsrc[j] + kb);
            }
            cp_commit();
        }

        unsigned sb = sbase + (kt % NSTAGE) * STAGE_WORDS * 4;
        // batch ALL fragment loads for both ks halves (16 LDSM), then mma
        unsigned af[2][4][4], bf[2][8][2];
#pragma unroll
        for (int ks = 0; ks < 2; ks++) {
#pragma unroll
            for (int i = 0; i < 4; i++)
                ldsm4(af[ks][i], sb + a_lane + (i * 16 * AW + ks * 8) * 4);
#pragma unroll
            for (int jp = 0; jp < 4; jp++) {
                unsigned rr[4];
                ldsm4t(rr, sb + b_lane + ks * 16 * (BW * 4) + jp * 32);
                bf[ks][2 * jp][0] = rr[0]; bf[ks][2 * jp][1] = rr[1];
                bf[ks][2 * jp + 1][0] = rr[2]; bf[ks][2 * jp + 1][1] = rr[3];
            }
        }
#pragma unroll
        for (int ks = 0; ks < 2; ks++)
#pragma unroll
            for (int i = 0; i < 4; i++)
#pragma unroll
                for (int j = 0; j < 8; j++) mma16(acc[i][j], af[ks][i], bf[ks][j]);
    }

    // epilogue: bias + silu -> fp16
#pragma unroll
    for (int i = 0; i < 4; i++) {
        int mrowA = m0 + wm * 64 + i * 16 + r;
        int mrowB = mrowA + 8;
#pragma unroll
        for (int j = 0; j < 8; j++) {
            int ncol = n0 + wn * 64 + j * 8 + c * 2;
            float2 bb = *(const float2*)&b1[(size_t)e * FDIM + ncol];
            if (mrowA < cnt) {
                __half2 h = __floats2half2_rn(silu_f(acc[i][j][0] + bb.x),
                                              silu_f(acc[i][j][1] + bb.y));
                *(__half2*)&g_h1f[(size_t)(off + mrowA) * FDIM + ncol] = h;
            }
            if (mrowB < cnt) {
                __half2 h = __floats2half2_rn(silu_f(acc[i][j][2] + bb.x),
                                              silu_f(acc[i][j][3] + bb.y));
                *(__half2*)&g_h1f[(size_t)(off + mrowB) * FDIM + ncol] = h;
            }
        }
    }
}

// GEMM2: out[tok[m]][n] += wt[m] * ( sum_k h1f[off+m][k] * w2h[e][k][n] + b2[e][n] )
__global__ void __launch_bounds__(128, 2)
gemm2_kernel(const float* __restrict__ b2, float* __restrict__ out) {
    int e = blockIdx.z;
    int cnt = g_count[e];
    int m0 = blockIdx.y * BM;
    if (m0 >= cnt) return;
    int n0 = blockIdx.x * BN;
    int off = g_off[e];

    extern __shared__ unsigned smw[];
    __shared__ int tks[BM];
    __shared__ float wts[BM];

    int tid = threadIdx.x;
    int wid = tid >> 5, lane = tid & 31;

    if (tid < BM) {
        int r = m0 + tid; if (r > cnt - 1) r = cnt - 1;
        tks[tid] = g_tok[e * NTOK + r];
        wts[tid] = g_wt[e * NTOK + r];
    }
    __syncthreads();

    unsigned sbase = su32(smw);
    unsigned adst[4], bdst[4];
    const char* asrc[4];
    const char* bsrc[4];
#pragma unroll
    for (int j = 0; j < 4; j++) {
        int idx = tid + 128 * j;
        int arow = idx >> 2, ach = idx & 3;
        int rr = m0 + arow; if (rr > cnt - 1) rr = cnt - 1;
        adst[j] = sbase + (arow * AW + ach * 4) * 4;
        asrc[j] = (const char*)(g_h1f + (size_t)(off + rr) * FDIM) + ach * 16;
        int brow = idx >> 4, bch = idx & 15;
        bdst[j] = sbase + (A_WORDS + brow * BW + bch * 4) * 4;
        bsrc[j] = (const char*)(g_w2h + (size_t)e * FDIM * HDIM + (size_t)brow * HDIM + n0) + bch * 16;
    }
    const size_t aadv = (size_t)BK * 2;
    const size_t badv = (size_t)BK * HDIM * 2;

    int wm = wid >> 1, wn = wid & 1;
    int t8 = lane >> 3, rit = lane & 7;
    unsigned a_lane = ((wm * 64 + (t8 & 1) * 8 + rit) * AW + (t8 >> 1) * 4) * 4;
    unsigned b_lane = A_WORDS * 4 + ((t8 & 1) * 8 + rit) * (BW * 4) + (wn * 64 + (t8 >> 1) * 8) * 2;

    float acc[4][8][4];
#pragma unroll
    for (int i = 0; i < 4; i++)
#pragma unroll
        for (int j = 0; j < 8; j++)
#pragma unroll
            for (int q = 0; q < 4; q++) acc[i][j][q] = 0.0f;

    const int NKT = FDIM / BK;  // 128
#pragma unroll
    for (int s = 0; s < NSTAGE - 1; s++) {
        unsigned so = s * STAGE_WORDS * 4;
#pragma unroll
        for (int j = 0; j < 4; j++) {
            cp_async16(adst[j] + so, asrc[j] + (size_t)s * aadv);
            cp_async16(bdst[j] + so, bsrc[j] + (size_t)s * badv);
        }
        cp_commit();
    }

    int r = lane >> 2, c = lane & 3;

    for (int kt = 0; kt < NKT; kt++) {
        if (kt < NKT - 2) cp_wait<2>();
        else if (kt == NKT - 2) cp_wait<1>();
        else cp_wait<0>();
        __syncthreads();

        if (kt + 3 < NKT) {
            unsigned so = ((kt + 3) % NSTAGE) * STAGE_WORDS * 4;
            size_t ka = (size_t)(kt + 3) * aadv;
            size_t kb = (size_t)(kt + 3) * badv;
#pragma unroll
            for (int j = 0; j < 4; j++) {
                cp_async16(adst[j] + so, asrc[j] + ka);
                cp_async16(bdst[j] + so, bsrc[j] + kb);
            }
            cp_commit();
        }

        unsigned sb = sbase + (kt % NSTAGE) * STAGE_WORDS * 4;
        unsigned af[2][4][4], bf[2][8][2];
#pragma unroll
        for (int ks = 0; ks < 2; ks++) {
#pragma unroll
            for (int i = 0; i < 4; i++)
                ldsm4(af[ks][i], sb + a_lane + (i * 16 * AW + ks * 8) * 4);
#pragma unroll
            for (int jp = 0; jp < 4; jp++) {
                unsigned rr[4];
                ldsm4t(rr, sb + b_lane + ks * 16 * (BW * 4) + jp * 32);
                bf[ks][2 * jp][0] = rr[0]; bf[ks][2 * jp][1] = rr[1];
                bf[ks][2 * jp + 1][0] = rr[2]; bf[ks][2 * jp + 1][1] = rr[3];
            }
        }
#pragma unroll
        for (int ks = 0; ks < 2; ks++)
#pragma unroll
            for (int i = 0; i < 4; i++)
#pragma unroll
                for (int j = 0; j < 8; j++) mma16(acc[i][j], af[ks][i], bf[ks][j]);
    }

#pragma unroll
    for (int i = 0; i < 4; i++) {
        int lrowA = wm * 64 + i * 16 + r;
        int lrowB = lrowA + 8;
        int mrowA = m0 + lrowA, mrowB = m0 + lrowB;
#pragma unroll
        for (int j = 0; j < 8; j++) {
            int ncol = n0 + wn * 64 + j * 8 + c * 2;
            float2 bb = *(const float2*)&b2[(size_t)e * HDIM + ncol];
            if (mrowA < cnt) {
                float w = wts[lrowA];
                float* op = out + (size_t)tks[lrowA] * HDIM + ncol;
                atomicAdd(op + 0, w * (acc[i][j][0] + bb.x));
                atomicAdd(op + 1, w * (acc[i][j][1] + bb.y));
            }
            if (mrowB < cnt) {
                float w = wts[lrowB];
                float* op = out + (size_t)tks[lrowB] * HDIM + ncol;
                atomicAdd(op + 0, w * (acc[i][j][2] + bb.x));
                atomicAdd(op + 1, w * (acc[i][j][3] + bb.y));
            }
        }
    }
}

// ---------------- launch ----------------
extern "C" void kernel_launch(void* const* d_in, const int* in_sizes, int n_in,
                              void* d_out, int out_size) {
    const float* x  = (const float*)d_in[0];
    const float* gw = (const float*)d_in[1];
    const float* w1 = (const float*)d_in[2];
    const float* b1 = (const float*)d_in[3];
    const float* w2 = (const float*)d_in[4];
    const float* b2 = (const float*)d_in[5];
    float* out = (float*)d_out;

    cudaFuncSetAttribute(gemm1_kernel, cudaFuncAttributeMaxDynamicSharedMemorySize, DYN_SMEM);
    cudaFuncSetAttribute(gemm2_kernel, cudaFuncAttributeMaxDynamicSharedMemorySize, DYN_SMEM);

    __half* xh;  cudaGetSymbolAddress((void**)&xh,  g_xh);
    __half* w1h; cudaGetSymbolAddress((void**)&w1h, g_w1h);
    __half* w2h; cudaGetSymbolAddress((void**)&w2h, g_w2h);

    zero_kernel<<<2048, 256>>>(out, out_size);
    reset_kernel<<<1, 32>>>();
    cvt16_kernel<<<1024, 256>>>(x, xh, (size_t)NTOK * HDIM);
    cvt16_kernel<<<4096, 256>>>(w1, w1h, (size_t)NE * HDIM * FDIM);
    cvt16_kernel<<<4096, 256>>>(w2, w2h, (size_t)NE * FDIM * HDIM);
    router_kernel<<<NTOK / 8, 256>>>(x, gw);
    partial_kernel<<<16, 256>>>();
    finalize_kernel<<<1, 32>>>(out, out_size);
    gemm1_kernel<<<dim3(FDIM / BN, NTOK / BM, NE), 128, DYN_SMEM>>>(b1);
    gemm2_kernel<<<dim3(HDIM / BN, NTOK / BM, NE), 128, DYN_SMEM>>>(b2, out);
}